// round 5
// baseline (speedup 1.0000x reference)
#include <cuda_runtime.h>
#include <cstdint>

// Problem constants
#define Bv 8
#define Vv 256
#define Hv 128
#define ROWS (Bv*Vv)          // 2048
#define H4 (Hv/4)             // 32 float4 per row

typedef unsigned long long ull;

// Intermediates (device globals; no allocation allowed)
__device__ float g_h0[ROWS*Hv];                 // silu(h @ W_pre + b_pre)
__device__ float g_sk[ROWS*Hv];                 // silu(h @ W_skip + b_skip)
__device__ float g_part[2*ROWS*Hv];             // neigh partial maxes (2 j-halves)

__device__ __forceinline__ float silu_f(float x) {
    return x * (1.0f / (1.0f + __expf(-x)));
}

__device__ __forceinline__ void cp16(uint32_t dst, const void* src) {
    asm volatile("cp.async.cg.shared.global [%0], [%1], 16;" :: "r"(dst), "l"(src));
}
__device__ __forceinline__ void cp_commit() {
    asm volatile("cp.async.commit_group;");
}

__device__ __forceinline__ ull ffma2(ull a, ull b, ull c) {
    ull d;
    asm("fma.rn.f32x2 %0, %1, %2, %3;" : "=l"(d) : "l"(a), "l"(b), "l"(c));
    return d;
}
__device__ __forceinline__ ull pack2(float x, float y) {
    ull d; asm("mov.b64 %0, {%1, %2};" : "=l"(d) : "f"(x), "f"(y)); return d;
}
__device__ __forceinline__ float2 unpack2(ull v) {
    float2 r; asm("mov.b64 {%0, %1}, %2;" : "=f"(r.x), "=f"(r.y) : "l"(v)); return r;
}

// ---------------------------------------------------------------------------
// Kernel A: h0 = silu(h @ W_pre + b_pre), sk = silu(h @ W_skip + b_skip)
// Warp-per-row direct-LDG GEMM: 512 blocks x 128 thr (4 warps = 4 rows).
// Lane owns 4 cols. Per k: one coalesced LDG.128 of W[k][lane*4] per matrix
// (W is L1-resident, 64KB) + one broadcast LDS of h[row][k]. No syncs in loop.
// ---------------------------------------------------------------------------
__global__ void __launch_bounds__(128) pre_kernel(
    const float* __restrict__ h,
    const float* __restrict__ Wpre,  const float* __restrict__ bpre,
    const float* __restrict__ Wskip, const float* __restrict__ bskip)
{
    __shared__ float hs[4][Hv];          // 2 KB

    const int tid  = threadIdx.x;
    const int w    = tid >> 5;           // row within block
    const int lane = tid & 31;           // col group (4 cols)
    const int row0 = blockIdx.x * 4;

    // stage 4 h rows: 128 float4, one per thread
    ((float4*)hs)[tid] = ((const float4*)h)[row0 * H4 + tid];
    __syncthreads();

    const float4* WA = (const float4*)Wpre  + lane;
    const float4* WB = (const float4*)Wskip + lane;
    const float*  hr = hs[w];

    ull accA01, accA23, accB01, accB23;
    {
        float4 bA = ((const float4*)bpre)[lane];
        float4 bB = ((const float4*)bskip)[lane];
        accA01 = pack2(bA.x, bA.y); accA23 = pack2(bA.z, bA.w);
        accB01 = pack2(bB.x, bB.y); accB23 = pack2(bB.z, bB.w);
    }

#pragma unroll 8
    for (int k = 0; k < Hv; k++) {
        const float hv = hr[k];
        const ull h2 = pack2(hv, hv);
        float4 wa = WA[k * H4];
        float4 wb = WB[k * H4];
        accA01 = ffma2(pack2(wa.x, wa.y), h2, accA01);
        accA23 = ffma2(pack2(wa.z, wa.w), h2, accA23);
        accB01 = ffma2(pack2(wb.x, wb.y), h2, accB01);
        accB23 = ffma2(pack2(wb.z, wb.w), h2, accB23);
    }

    {
        float2 a01 = unpack2(accA01), a23 = unpack2(accA23);
        float2 b01 = unpack2(accB01), b23 = unpack2(accB23);
        float4 oA = make_float4(silu_f(a01.x), silu_f(a01.y), silu_f(a23.x), silu_f(a23.y));
        float4 oB = make_float4(silu_f(b01.x), silu_f(b01.y), silu_f(b23.x), silu_f(b23.y));
        ((float4*)g_h0)[(row0 + w) * H4 + lane] = oA;
        ((float4*)g_sk)[(row0 + w) * H4 + lane] = oB;
    }
}

// ---------------------------------------------------------------------------
// Kernel B (dominant): partial neigh max over a 128-wide j-half.
// 512 blocks (b x 32 i-tiles x 2 j-halves) x 256 threads -> ALL resident
// (36 KB smem/block, no wave tail). h0 staged via cp.async double buffer.
// ---------------------------------------------------------------------------
__global__ void __launch_bounds__(256) agg_kernel(
    const float* __restrict__ e,
    const int*   __restrict__ graph)
{
    __shared__ float4 h0s[2][32 * H4];   // 2 x 16 KB
    __shared__ int    gsh[8][128];       // 4 KB

    const int tid  = threadIdx.x;
    const int hq   = tid & 31;           // float4 index in H
    const int isub = tid >> 5;           // 0..7
    const int b    = blockIdx.x >> 6;
    const int rem  = blockIdx.x & 63;
    const int i0   = (rem >> 1) * 8;
    const int jh   = rem & 1;
    const int j0   = jh * 128;
    const int i    = i0 + isub;

    // stage graph mask for this (i-tile, j-half): 1024 ints, 4/thread
#pragma unroll
    for (int x = tid; x < 8 * 128; x += 256) {
        gsh[x >> 7][x & 127] = graph[(b * Vv + i0 + (x >> 7)) * Vv + j0 + (x & 127)];
    }

    const float4* H0 = (const float4*)g_h0 + b * Vv * H4 + j0 * H4;
    const uint32_t sb0 = (uint32_t)__cvta_generic_to_shared(&h0s[0][0]);
    const uint32_t sb1 = (uint32_t)__cvta_generic_to_shared(&h0s[1][0]);

    // issue chunk c (32 j x 32 q = 1024 float4; 4 cp.async per thread)
    auto issue = [&](int c) {
        const uint32_t sb = (c & 1) ? sb1 : sb0;
#pragma unroll
        for (int r = 0; r < 4; r++) {
            const int x = r * 256 + tid;
            cp16(sb + x * 16, (const void*)(H0 + c * 1024 + x));
        }
        cp_commit();
    };
    issue(0);
    issue(1);

    const float4* Ep = (const float4*)e + ((size_t)(b * Vv + i) * Vv + j0) * H4 + hq;

    const float NEG_INF = __int_as_float(0xff800000);
    float4 acc = make_float4(NEG_INF, NEG_INF, NEG_INF, NEG_INF);

    for (int c = 0; c < 4; c++) {
        if (c == 3) asm volatile("cp.async.wait_group 0;");
        else        asm volatile("cp.async.wait_group 1;");
        __syncthreads();

        const float4* hb = h0s[c & 1];
        const int*    gm = &gsh[isub][c * 32];

#pragma unroll 8
        for (int jj = 0; jj < 32; jj++) {
            float4 ev = Ep[jj * H4];
            float4 hv = hb[jj * H4 + hq];
            if (gm[jj] != 0) { hv.x = 0.f; hv.y = 0.f; hv.z = 0.f; hv.w = 0.f; }
            acc.x = fmaxf(acc.x, ev.x * hv.x);
            acc.y = fmaxf(acc.y, ev.y * hv.y);
            acc.z = fmaxf(acc.z, ev.z * hv.z);
            acc.w = fmaxf(acc.w, ev.w * hv.w);
        }
        Ep += 32 * H4;

        __syncthreads();
        if (c + 2 < 4) issue(c + 2);
    }

    ((float4*)g_part)[((size_t)jh * ROWS + b * Vv + i) * H4 + hq] = acc;
}

// ---------------------------------------------------------------------------
// Kernel C: out = silu( sk + silu([h0,neigh] @ W_post + b_post) )
// Warp-per-row direct-LDG GEMM, K=256. 512 blocks x 128 thr (4 rows).
// neigh = max of the two j-half partials, folded in during staging.
// ---------------------------------------------------------------------------
__global__ void __launch_bounds__(128) post_kernel(
    const float* __restrict__ Wpost, const float* __restrict__ bpost,
    float* __restrict__ out)
{
    __shared__ float a0[4][Hv];          // h0 rows
    __shared__ float a1[4][Hv];          // neigh rows

    const int tid  = threadIdx.x;
    const int w    = tid >> 5;
    const int lane = tid & 31;
    const int row0 = blockIdx.x * 4;

    // stage: 128 float4 each, one per thread (+ partial-max fold)
    {
        const float4* gp = (const float4*)g_part;
        ((float4*)a0)[tid] = ((const float4*)g_h0)[row0 * H4 + tid];
        float4 p0 = gp[row0 * H4 + tid];
        float4 p1 = gp[(size_t)ROWS * H4 + row0 * H4 + tid];
        ((float4*)a1)[tid] = make_float4(fmaxf(p0.x, p1.x), fmaxf(p0.y, p1.y),
                                         fmaxf(p0.z, p1.z), fmaxf(p0.w, p1.w));
    }
    __syncthreads();

    const float4* W1 = (const float4*)Wpost + lane;              // k in [0,128)
    const float4* W2 = (const float4*)Wpost + Hv * H4 + lane;    // k in [128,256)
    const float*  r0p = a0[w];
    const float*  r1p = a1[w];

    ull acc01, acc23;
    {
        float4 bP = ((const float4*)bpost)[lane];
        acc01 = pack2(bP.x, bP.y); acc23 = pack2(bP.z, bP.w);
    }

#pragma unroll 8
    for (int k = 0; k < Hv; k++) {
        const float av = r0p[k];
        const ull a2 = pack2(av, av);
        float4 w1 = W1[k * H4];
        acc01 = ffma2(pack2(w1.x, w1.y), a2, acc01);
        acc23 = ffma2(pack2(w1.z, w1.w), a2, acc23);
        const float bv = r1p[k];
        const ull b2 = pack2(bv, bv);
        float4 w2 = W2[k * H4];
        acc01 = ffma2(pack2(w2.x, w2.y), b2, acc01);
        acc23 = ffma2(pack2(w2.z, w2.w), b2, acc23);
    }

    {
        const int row = row0 + w;
        float2 v01 = unpack2(acc01), v23 = unpack2(acc23);
        float4 sk = ((const float4*)g_sk)[row * H4 + lane];
        float4 o;
        o.x = silu_f(sk.x + silu_f(v01.x));
        o.y = silu_f(sk.y + silu_f(v01.y));
        o.z = silu_f(sk.z + silu_f(v23.x));
        o.w = silu_f(sk.w + silu_f(v23.y));
        ((float4*)out)[row * H4 + lane] = o;
    }
}

// ---------------------------------------------------------------------------
extern "C" void kernel_launch(void* const* d_in, const int* in_sizes, int n_in,
                              void* d_out, int out_size)
{
    const float* h     = (const float*)d_in[0];
    const float* e     = (const float*)d_in[1];
    const int*   graph = (const int*)  d_in[2];
    const float* Wpre  = (const float*)d_in[3];
    const float* bpre  = (const float*)d_in[4];
    const float* Wpost = (const float*)d_in[5];
    const float* bpost = (const float*)d_in[6];
    const float* Wskip = (const float*)d_in[7];
    const float* bskip = (const float*)d_in[8];
    float* out = (float*)d_out;

    pre_kernel<<<ROWS / 4, 128>>>(h, Wpre, bpre, Wskip, bskip);
    agg_kernel<<<(ROWS / 8) * 2, 256>>>(e, graph);
    post_kernel<<<ROWS / 4, 128>>>(Wpost, bpost, out);
}

// round 7
// speedup vs baseline: 1.7635x; 1.7635x over previous
#include <cuda_runtime.h>
#include <cstdint>

// Problem constants
#define Bv 8
#define Vv 256
#define Hv 128
#define ROWS (Bv*Vv)          // 2048
#define H4 (Hv/4)             // 32 float4 per row

typedef unsigned long long ull;

// Intermediates (device globals; no allocation allowed)
__device__ float g_h0[ROWS*Hv];                 // silu(h @ W_pre + b_pre)
__device__ float g_sk[ROWS*Hv];                 // silu(h @ W_skip + b_skip)
__device__ float g_part[2*ROWS*Hv];             // neigh partial maxes (2 j-halves)

__device__ __forceinline__ float silu_f(float x) {
    return x * (1.0f / (1.0f + __expf(-x)));
}

__device__ __forceinline__ void cp16(uint32_t dst, const void* src) {
    asm volatile("cp.async.cg.shared.global [%0], [%1], 16;" :: "r"(dst), "l"(src));
}
__device__ __forceinline__ void cp_commit() {
    asm volatile("cp.async.commit_group;");
}

__device__ __forceinline__ ull ffma2(ull a, ull b, ull c) {
    ull d;
    asm("fma.rn.f32x2 %0, %1, %2, %3;" : "=l"(d) : "l"(a), "l"(b), "l"(c));
    return d;
}
__device__ __forceinline__ ull pack2(float x, float y) {
    ull d; asm("mov.b64 %0, {%1, %2};" : "=l"(d) : "f"(x), "f"(y)); return d;
}
__device__ __forceinline__ float2 unpack2(ull v) {
    float2 r; asm("mov.b64 {%0, %1}, %2;" : "=f"(r.x), "=f"(r.y) : "l"(v)); return r;
}

// ---------------------------------------------------------------------------
// Kernel A: h0 = silu(h @ W_pre + b_pre), sk = silu(h @ W_skip + b_skip)
// 256 blocks x 256 threads, 8 rows/block. ALL of W_pre+W_skip burst-loaded
// into smem (128 KB, 4096 float4 EACH -> 16/thread each) with one sync, then
// a straight 128-k loop with no synchronization.
// Thread: col = tid&127, 4 rows (two f32x2 pairs) per matrix via FFMA2.
// Dynamic smem: [WA 16K floats][WB 16K floats][hT 128][8]] = 132 KB.
// ---------------------------------------------------------------------------
extern __shared__ float s_dyn[];

__global__ void __launch_bounds__(256) pre_kernel(
    const float* __restrict__ h,
    const float* __restrict__ Wpre,  const float* __restrict__ bpre,
    const float* __restrict__ Wskip, const float* __restrict__ bskip)
{
    float* sWA = s_dyn;                       // 128*128
    float* sWB = s_dyn + Hv * Hv;             // 128*128
    float* hT  = s_dyn + 2 * Hv * Hv;         // hT[k][8]

    const int tid  = threadIdx.x;
    const int c    = tid & 127;
    const int r0   = (tid >> 7) * 4;          // 0 or 4
    const int row0 = blockIdx.x * 8;

    // Burst-load both W matrices: 4096 float4 each, 16/thread each, full MLP.
    const float4* WAg = (const float4*)Wpre;
    const float4* WBg = (const float4*)Wskip;
#pragma unroll
    for (int r = 0; r < 16; r++) {
        const int x = r * 256 + tid;
        ((float4*)sWA)[x] = WAg[x];
        ((float4*)sWB)[x] = WBg[x];
    }

    // Stage transposed h rows: 8 rows x 32 float4 = 256, one per thread.
    {
        const int rr = tid & 7, k4 = tid >> 3;
        float4 v = ((const float4*)h)[(row0 + rr) * H4 + k4];
        hT[(k4 * 4 + 0) * 8 + rr] = v.x;
        hT[(k4 * 4 + 1) * 8 + rr] = v.y;
        hT[(k4 * 4 + 2) * 8 + rr] = v.z;
        hT[(k4 * 4 + 3) * 8 + rr] = v.w;
    }
    __syncthreads();

    ull accA0, accA1, accB0, accB1;
    {
        const float bA = bpre[c], bB = bskip[c];
        accA0 = pack2(bA, bA); accA1 = accA0;
        accB0 = pack2(bB, bB); accB1 = accB0;
    }

#pragma unroll 16
    for (int k = 0; k < Hv; k++) {
        const float wa = sWA[k * Hv + c];
        const float wb = sWB[k * Hv + c];
        ulonglong2 hv = *(const ulonglong2*)&hT[k * 8 + r0];  // rows r0..r0+3
        const ull wa2 = pack2(wa, wa);
        const ull wb2 = pack2(wb, wb);
        accA0 = ffma2(hv.x, wa2, accA0);
        accA1 = ffma2(hv.y, wa2, accA1);
        accB0 = ffma2(hv.x, wb2, accB0);
        accB1 = ffma2(hv.y, wb2, accB1);
    }

    {
        float2 a0 = unpack2(accA0), a1 = unpack2(accA1);
        float2 b0 = unpack2(accB0), b1 = unpack2(accB1);
        const int row = row0 + r0;
        g_h0[(row + 0) * Hv + c] = silu_f(a0.x);
        g_h0[(row + 1) * Hv + c] = silu_f(a0.y);
        g_h0[(row + 2) * Hv + c] = silu_f(a1.x);
        g_h0[(row + 3) * Hv + c] = silu_f(a1.y);
        g_sk[(row + 0) * Hv + c] = silu_f(b0.x);
        g_sk[(row + 1) * Hv + c] = silu_f(b0.y);
        g_sk[(row + 2) * Hv + c] = silu_f(b1.x);
        g_sk[(row + 3) * Hv + c] = silu_f(b1.y);
    }
}

// ---------------------------------------------------------------------------
// Kernel B (dominant): partial neigh max over a 128-wide j-half.
// 512 blocks (b x 32 i-tiles x 2 j-halves) x 256 threads -> ALL resident
// (36 KB smem/block, no wave tail). h0 staged via cp.async double buffer.
// ---------------------------------------------------------------------------
__global__ void __launch_bounds__(256) agg_kernel(
    const float* __restrict__ e,
    const int*   __restrict__ graph)
{
    __shared__ float4 h0s[2][32 * H4];   // 2 x 16 KB
    __shared__ int    gsh[8][128];       // 4 KB

    const int tid  = threadIdx.x;
    const int hq   = tid & 31;           // float4 index in H
    const int isub = tid >> 5;           // 0..7
    const int b    = blockIdx.x >> 6;
    const int rem  = blockIdx.x & 63;
    const int i0   = (rem >> 1) * 8;
    const int jh   = rem & 1;
    const int j0   = jh * 128;
    const int i    = i0 + isub;

    // stage graph mask for this (i-tile, j-half): 1024 ints, 4/thread
#pragma unroll
    for (int x = tid; x < 8 * 128; x += 256) {
        gsh[x >> 7][x & 127] = graph[(b * Vv + i0 + (x >> 7)) * Vv + j0 + (x & 127)];
    }

    const float4* H0 = (const float4*)g_h0 + b * Vv * H4 + j0 * H4;
    const uint32_t sb0 = (uint32_t)__cvta_generic_to_shared(&h0s[0][0]);
    const uint32_t sb1 = (uint32_t)__cvta_generic_to_shared(&h0s[1][0]);

    // issue chunk c (32 j x 32 q = 1024 float4; 4 cp.async per thread)
    auto issue = [&](int c) {
        const uint32_t sb = (c & 1) ? sb1 : sb0;
#pragma unroll
        for (int r = 0; r < 4; r++) {
            const int x = r * 256 + tid;
            cp16(sb + x * 16, (const void*)(H0 + c * 1024 + x));
        }
        cp_commit();
    };
    issue(0);
    issue(1);

    const float4* Ep = (const float4*)e + ((size_t)(b * Vv + i) * Vv + j0) * H4 + hq;

    const float NEG_INF = __int_as_float(0xff800000);
    float4 acc = make_float4(NEG_INF, NEG_INF, NEG_INF, NEG_INF);

    for (int c = 0; c < 4; c++) {
        if (c == 3) asm volatile("cp.async.wait_group 0;");
        else        asm volatile("cp.async.wait_group 1;");
        __syncthreads();

        const float4* hb = h0s[c & 1];
        const int*    gm = &gsh[isub][c * 32];

#pragma unroll 8
        for (int jj = 0; jj < 32; jj++) {
            float4 ev = Ep[jj * H4];
            float4 hv = hb[jj * H4 + hq];
            if (gm[jj] != 0) { hv.x = 0.f; hv.y = 0.f; hv.z = 0.f; hv.w = 0.f; }
            acc.x = fmaxf(acc.x, ev.x * hv.x);
            acc.y = fmaxf(acc.y, ev.y * hv.y);
            acc.z = fmaxf(acc.z, ev.z * hv.z);
            acc.w = fmaxf(acc.w, ev.w * hv.w);
        }
        Ep += 32 * H4;

        __syncthreads();
        if (c + 2 < 4) issue(c + 2);
    }

    ((float4*)g_part)[((size_t)jh * ROWS + b * Vv + i) * H4 + hq] = acc;
}

// ---------------------------------------------------------------------------
// Kernel C: out = silu( sk + silu([h0,neigh] @ W_post + b_post) )
// 128 blocks x 256 threads, 16 rows/block. ALL of W_post (128 KB, 8192
// float4 -> 32/thread) burst-loaded into smem, activations transposed
// (aT[k][16], k<128 h0, k>=128 neigh = max of partials). One sync, then
// straight 256-k loop. Dynamic smem: [W 32K floats][aT 256][16]] = 144 KB.
// ---------------------------------------------------------------------------
__global__ void __launch_bounds__(256) post_kernel(
    const float* __restrict__ Wpost, const float* __restrict__ bpost,
    float* __restrict__ out)
{
    float* sW = s_dyn;                        // 256*128
    float* aT = s_dyn + 2 * Hv * Hv;          // aT[k][16]

    const int tid  = threadIdx.x;
    const int c    = tid & 127;
    const int r0   = (tid >> 7) * 8;          // 0 or 8
    const int row0 = blockIdx.x * 16;

    // Burst-load W_post: 8192 float4, 32/thread.
    const float4* Wg = (const float4*)Wpost;
#pragma unroll
    for (int r = 0; r < 32; r++) {
        const int x = r * 256 + tid;
        ((float4*)sW)[x] = Wg[x];
    }

    // Stage transposed h0 and neigh: 512 float4 each, 2/thread each.
    const float4* h04 = (const float4*)g_h0;
    const float4* gp  = (const float4*)g_part;
#pragma unroll
    for (int x = tid; x < 512; x += 256) {
        const int rr = x & 15, k4 = x >> 4;
        float4 v = h04[(row0 + rr) * H4 + k4];
        aT[(k4 * 4 + 0) * 16 + rr] = v.x;
        aT[(k4 * 4 + 1) * 16 + rr] = v.y;
        aT[(k4 * 4 + 2) * 16 + rr] = v.z;
        aT[(k4 * 4 + 3) * 16 + rr] = v.w;
        float4 p0 = gp[(row0 + rr) * H4 + k4];
        float4 p1 = gp[(size_t)ROWS * H4 + (row0 + rr) * H4 + k4];
        aT[(Hv + k4 * 4 + 0) * 16 + rr] = fmaxf(p0.x, p1.x);
        aT[(Hv + k4 * 4 + 1) * 16 + rr] = fmaxf(p0.y, p1.y);
        aT[(Hv + k4 * 4 + 2) * 16 + rr] = fmaxf(p0.z, p1.z);
        aT[(Hv + k4 * 4 + 3) * 16 + rr] = fmaxf(p0.w, p1.w);
    }
    __syncthreads();

    ull acc0, acc1, acc2, acc3;
    {
        const float bP = bpost[c];
        acc0 = pack2(bP, bP); acc1 = acc0; acc2 = acc0; acc3 = acc0;
    }

#pragma unroll 16
    for (int k = 0; k < 2 * Hv; k++) {
        const float w = sW[k * Hv + c];
        ulonglong2 aLo = *(const ulonglong2*)&aT[k * 16 + r0];      // rows r0..r0+3
        ulonglong2 aHi = *(const ulonglong2*)&aT[k * 16 + r0 + 4];  // rows r0+4..r0+7
        const ull w2 = pack2(w, w);
        acc0 = ffma2(aLo.x, w2, acc0);
        acc1 = ffma2(aLo.y, w2, acc1);
        acc2 = ffma2(aHi.x, w2, acc2);
        acc3 = ffma2(aHi.y, w2, acc3);
    }

    {
        float2 v0 = unpack2(acc0), v1 = unpack2(acc1);
        float2 v2 = unpack2(acc2), v3 = unpack2(acc3);
        const int row = row0 + r0;
        out[(row + 0) * Hv + c] = silu_f(g_sk[(row + 0) * Hv + c] + silu_f(v0.x));
        out[(row + 1) * Hv + c] = silu_f(g_sk[(row + 1) * Hv + c] + silu_f(v0.y));
        out[(row + 2) * Hv + c] = silu_f(g_sk[(row + 2) * Hv + c] + silu_f(v1.x));
        out[(row + 3) * Hv + c] = silu_f(g_sk[(row + 3) * Hv + c] + silu_f(v1.y));
        out[(row + 4) * Hv + c] = silu_f(g_sk[(row + 4) * Hv + c] + silu_f(v2.x));
        out[(row + 5) * Hv + c] = silu_f(g_sk[(row + 5) * Hv + c] + silu_f(v2.y));
        out[(row + 6) * Hv + c] = silu_f(g_sk[(row + 6) * Hv + c] + silu_f(v3.x));
        out[(row + 7) * Hv + c] = silu_f(g_sk[(row + 7) * Hv + c] + silu_f(v3.y));
    }
}

// ---------------------------------------------------------------------------
extern "C" void kernel_launch(void* const* d_in, const int* in_sizes, int n_in,
                              void* d_out, int out_size)
{
    const float* h     = (const float*)d_in[0];
    const float* e     = (const float*)d_in[1];
    const int*   graph = (const int*)  d_in[2];
    const float* Wpre  = (const float*)d_in[3];
    const float* bpre  = (const float*)d_in[4];
    const float* Wpost = (const float*)d_in[5];
    const float* bpost = (const float*)d_in[6];
    const float* Wskip = (const float*)d_in[7];
    const float* bskip = (const float*)d_in[8];
    float* out = (float*)d_out;

    const int preSmem  = (2 * Hv * Hv + Hv * 8) * 4;          // 132 KB
    const int postSmem = (2 * Hv * Hv + 2 * Hv * 16) * 4;     // 144 KB
    cudaFuncSetAttribute(pre_kernel,  cudaFuncAttributeMaxDynamicSharedMemorySize, preSmem);
    cudaFuncSetAttribute(post_kernel, cudaFuncAttributeMaxDynamicSharedMemorySize, postSmem);

    pre_kernel<<<ROWS / 8, 256, preSmem>>>(h, Wpre, bpre, Wskip, bskip);
    agg_kernel<<<(ROWS / 8) * 2, 256>>>(e, graph);
    post_kernel<<<ROWS / 16, 256, postSmem>>>(Wpost, bpost, out);
}

// round 8
// speedup vs baseline: 1.8013x; 1.0214x over previous
#include <cuda_runtime.h>
#include <cstdint>

// Problem constants
#define Bv 8
#define Vv 256
#define Hv 128
#define ROWS (Bv*Vv)          // 2048
#define H4 (Hv/4)             // 32 float4 per row

typedef unsigned long long ull;

// Intermediates (device globals; no allocation allowed)
__device__ float g_h0[ROWS*Hv];                 // silu(h @ W_pre + b_pre)
__device__ float g_sk[ROWS*Hv];                 // silu(h @ W_skip + b_skip)
__device__ float g_part[2*ROWS*Hv];             // neigh partial maxes (2 j-halves)

__device__ __forceinline__ float silu_f(float x) {
    return x * (1.0f / (1.0f + __expf(-x)));
}

__device__ __forceinline__ void cp16(uint32_t dst, const void* src) {
    asm volatile("cp.async.cg.shared.global [%0], [%1], 16;" :: "r"(dst), "l"(src));
}
__device__ __forceinline__ void cp_commit() {
    asm volatile("cp.async.commit_group;");
}

__device__ __forceinline__ ull ffma2(ull a, ull b, ull c) {
    ull d;
    asm("fma.rn.f32x2 %0, %1, %2, %3;" : "=l"(d) : "l"(a), "l"(b), "l"(c));
    return d;
}
__device__ __forceinline__ ull pack2(float x, float y) {
    ull d; asm("mov.b64 %0, {%1, %2};" : "=l"(d) : "f"(x), "f"(y)); return d;
}
__device__ __forceinline__ float2 unpack2(ull v) {
    float2 r; asm("mov.b64 {%0, %1}, %2;" : "=f"(r.x), "=f"(r.y) : "l"(v)); return r;
}

// ---------------------------------------------------------------------------
// Kernel A: h0 = silu(h @ W_pre + b_pre), sk = silu(h @ W_skip + b_skip)
// 2-D tiled: 512 blocks (128 row-tiles x 4 col-tiles) x 256 threads.
// Block output = 16 rows x 32 cols (both matrices). W SLICE (128k x 32c per
// matrix, 16 KB each) staged once; one sync; straight 128-k loop, no barriers.
// Thread: c = tid&31 (col), rp = tid>>5 (row pair) -> 2 rows x 1 col x 2 mats.
// ---------------------------------------------------------------------------
__global__ void __launch_bounds__(256) pre_kernel(
    const float* __restrict__ h,
    const float* __restrict__ Wpre,  const float* __restrict__ bpre,
    const float* __restrict__ Wskip, const float* __restrict__ bskip)
{
    __shared__ float sWA[Hv * 32];       // 16 KB : sWA[k][c]
    __shared__ float sWB[Hv * 32];       // 16 KB
    __shared__ float hT[Hv * 16];        // 8 KB  : hT[k][r]

    const int tid  = threadIdx.x;
    const int c    = tid & 31;
    const int rp   = tid >> 5;           // 0..7 (row pair)
    const int rowT = blockIdx.x >> 2;
    const int colT = blockIdx.x & 3;
    const int row0 = rowT * 16;
    const int col0 = colT * 32;

    // Stage W slices: 1024 float4 each, 4/thread each.
    const float4* WAg = (const float4*)Wpre;
    const float4* WBg = (const float4*)Wskip;
#pragma unroll
    for (int r = 0; r < 4; r++) {
        const int x = r * 256 + tid;           // x = k*8 + c4
        const int src = (x >> 3) * 32 + colT * 8 + (x & 7);
        ((float4*)sWA)[x] = WAg[src];
        ((float4*)sWB)[x] = WBg[src];
    }

    // Stage transposed h rows: 16 rows x 32 float4 = 512, 2/thread.
    const float4* h4 = (const float4*)h;
#pragma unroll
    for (int x = tid; x < 512; x += 256) {
        const int rr = x & 15, k4 = x >> 4;
        float4 v = h4[(row0 + rr) * H4 + k4];
        hT[(k4 * 4 + 0) * 16 + rr] = v.x;
        hT[(k4 * 4 + 1) * 16 + rr] = v.y;
        hT[(k4 * 4 + 2) * 16 + rr] = v.z;
        hT[(k4 * 4 + 3) * 16 + rr] = v.w;
    }
    __syncthreads();

    ull accA, accB;
    {
        const float bA = bpre[col0 + c], bB = bskip[col0 + c];
        accA = pack2(bA, bA);
        accB = pack2(bB, bB);
    }

#pragma unroll 16
    for (int k = 0; k < Hv; k++) {
        ull h2 = *(const ull*)&hT[k * 16 + 2 * rp];   // rows 2rp, 2rp+1 (bcast)
        const float wa = sWA[k * 32 + c];
        const float wb = sWB[k * 32 + c];
        accA = ffma2(h2, pack2(wa, wa), accA);
        accB = ffma2(h2, pack2(wb, wb), accB);
    }

    {
        float2 a = unpack2(accA), b = unpack2(accB);
        const int row = row0 + 2 * rp;
        const int col = col0 + c;
        g_h0[row * Hv + col]       = silu_f(a.x);
        g_h0[(row + 1) * Hv + col] = silu_f(a.y);
        g_sk[row * Hv + col]       = silu_f(b.x);
        g_sk[(row + 1) * Hv + col] = silu_f(b.y);
    }
}

// ---------------------------------------------------------------------------
// Kernel B (dominant): partial neigh max over a 128-wide j-half.
// 512 blocks (b x 32 i-tiles x 2 j-halves) x 256 threads -> ALL resident
// (36 KB smem/block, no wave tail). h0 staged via cp.async double buffer.
// ---------------------------------------------------------------------------
__global__ void __launch_bounds__(256) agg_kernel(
    const float* __restrict__ e,
    const int*   __restrict__ graph)
{
    __shared__ float4 h0s[2][32 * H4];   // 2 x 16 KB
    __shared__ int    gsh[8][128];       // 4 KB

    const int tid  = threadIdx.x;
    const int hq   = tid & 31;           // float4 index in H
    const int isub = tid >> 5;           // 0..7
    const int b    = blockIdx.x >> 6;
    const int rem  = blockIdx.x & 63;
    const int i0   = (rem >> 1) * 8;
    const int jh   = rem & 1;
    const int j0   = jh * 128;
    const int i    = i0 + isub;

    // stage graph mask for this (i-tile, j-half): 1024 ints, 4/thread
#pragma unroll
    for (int x = tid; x < 8 * 128; x += 256) {
        gsh[x >> 7][x & 127] = graph[(b * Vv + i0 + (x >> 7)) * Vv + j0 + (x & 127)];
    }

    const float4* H0 = (const float4*)g_h0 + b * Vv * H4 + j0 * H4;
    const uint32_t sb0 = (uint32_t)__cvta_generic_to_shared(&h0s[0][0]);
    const uint32_t sb1 = (uint32_t)__cvta_generic_to_shared(&h0s[1][0]);

    // issue chunk c (32 j x 32 q = 1024 float4; 4 cp.async per thread)
    auto issue = [&](int c) {
        const uint32_t sb = (c & 1) ? sb1 : sb0;
#pragma unroll
        for (int r = 0; r < 4; r++) {
            const int x = r * 256 + tid;
            cp16(sb + x * 16, (const void*)(H0 + c * 1024 + x));
        }
        cp_commit();
    };
    issue(0);
    issue(1);

    const float4* Ep = (const float4*)e + ((size_t)(b * Vv + i) * Vv + j0) * H4 + hq;

    const float NEG_INF = __int_as_float(0xff800000);
    float4 acc = make_float4(NEG_INF, NEG_INF, NEG_INF, NEG_INF);

    for (int c = 0; c < 4; c++) {
        if (c == 3) asm volatile("cp.async.wait_group 0;");
        else        asm volatile("cp.async.wait_group 1;");
        __syncthreads();

        const float4* hb = h0s[c & 1];
        const int*    gm = &gsh[isub][c * 32];

#pragma unroll 8
        for (int jj = 0; jj < 32; jj++) {
            float4 ev = Ep[jj * H4];
            float4 hv = hb[jj * H4 + hq];
            if (gm[jj] != 0) { hv.x = 0.f; hv.y = 0.f; hv.z = 0.f; hv.w = 0.f; }
            acc.x = fmaxf(acc.x, ev.x * hv.x);
            acc.y = fmaxf(acc.y, ev.y * hv.y);
            acc.z = fmaxf(acc.z, ev.z * hv.z);
            acc.w = fmaxf(acc.w, ev.w * hv.w);
        }
        Ep += 32 * H4;

        __syncthreads();
        if (c + 2 < 4) issue(c + 2);
    }

    ((float4*)g_part)[((size_t)jh * ROWS + b * Vv + i) * H4 + hq] = acc;
}

// ---------------------------------------------------------------------------
// Kernel C: out = silu( sk + silu([h0,neigh] @ W_post + b_post) )
// 2-D tiled: 512 blocks (128 row-tiles x 4 col-tiles) x 256 threads.
// Block output = 16 rows x 32 cols. W_post SLICE (256k x 32c = 32 KB) staged;
// activations transposed (aT[k][16], k<128 h0, k>=128 neigh = max of
// partials). One sync; straight 256-k loop, two accumulator chains.
// Dynamic smem: [sW 256*32][aT 256*16] = 48 KB.
// ---------------------------------------------------------------------------
extern __shared__ float s_dyn[];

__global__ void __launch_bounds__(256) post_kernel(
    const float* __restrict__ Wpost, const float* __restrict__ bpost,
    float* __restrict__ out)
{
    float* sW = s_dyn;                    // sW[k][c], 256 x 32
    float* aT = s_dyn + 2 * Hv * 32;      // aT[k][r], 256 x 16

    const int tid  = threadIdx.x;
    const int c    = tid & 31;
    const int rp   = tid >> 5;            // 0..7
    const int rowT = blockIdx.x >> 2;
    const int colT = blockIdx.x & 3;
    const int row0 = rowT * 16;
    const int col0 = colT * 32;

    // Stage W slice: 2048 float4, 8/thread.
    const float4* Wg = (const float4*)Wpost;
#pragma unroll
    for (int r = 0; r < 8; r++) {
        const int x = r * 256 + tid;           // x = k*8 + c4
        ((float4*)sW)[x] = Wg[(x >> 3) * 32 + colT * 8 + (x & 7)];
    }

    // Stage transposed h0 and neigh: 512 float4 paths, 2/thread each.
    const float4* h04 = (const float4*)g_h0;
    const float4* gp  = (const float4*)g_part;
#pragma unroll
    for (int x = tid; x < 512; x += 256) {
        const int rr = x & 15, k4 = x >> 4;
        float4 v = h04[(row0 + rr) * H4 + k4];
        aT[(k4 * 4 + 0) * 16 + rr] = v.x;
        aT[(k4 * 4 + 1) * 16 + rr] = v.y;
        aT[(k4 * 4 + 2) * 16 + rr] = v.z;
        aT[(k4 * 4 + 3) * 16 + rr] = v.w;
        float4 p0 = gp[(row0 + rr) * H4 + k4];
        float4 p1 = gp[(size_t)ROWS * H4 + (row0 + rr) * H4 + k4];
        aT[(Hv + k4 * 4 + 0) * 16 + rr] = fmaxf(p0.x, p1.x);
        aT[(Hv + k4 * 4 + 1) * 16 + rr] = fmaxf(p0.y, p1.y);
        aT[(Hv + k4 * 4 + 2) * 16 + rr] = fmaxf(p0.z, p1.z);
        aT[(Hv + k4 * 4 + 3) * 16 + rr] = fmaxf(p0.w, p1.w);
    }
    __syncthreads();

    ull acc0, acc1;
    {
        const float bP = bpost[col0 + c];
        acc0 = pack2(bP, bP);
        acc1 = pack2(0.f, 0.f);
    }

#pragma unroll 16
    for (int k = 0; k < 2 * Hv; k += 2) {
        ull a2 = *(const ull*)&aT[k * 16 + 2 * rp];
        const float w0 = sW[k * 32 + c];
        acc0 = ffma2(a2, pack2(w0, w0), acc0);
        ull a3 = *(const ull*)&aT[(k + 1) * 16 + 2 * rp];
        const float w1 = sW[(k + 1) * 32 + c];
        acc1 = ffma2(a3, pack2(w1, w1), acc1);
    }

    {
        float2 v0 = unpack2(acc0), v1 = unpack2(acc1);
        const float vx = v0.x + v1.x;
        const float vy = v0.y + v1.y;
        const int row = row0 + 2 * rp;
        const int col = col0 + c;
        out[row * Hv + col]       = silu_f(g_sk[row * Hv + col]       + silu_f(vx));
        out[(row + 1) * Hv + col] = silu_f(g_sk[(row + 1) * Hv + col] + silu_f(vy));
    }
}

// ---------------------------------------------------------------------------
extern "C" void kernel_launch(void* const* d_in, const int* in_sizes, int n_in,
                              void* d_out, int out_size)
{
    const float* h     = (const float*)d_in[0];
    const float* e     = (const float*)d_in[1];
    const int*   graph = (const int*)  d_in[2];
    const float* Wpre  = (const float*)d_in[3];
    const float* bpre  = (const float*)d_in[4];
    const float* Wpost = (const float*)d_in[5];
    const float* bpost = (const float*)d_in[6];
    const float* Wskip = (const float*)d_in[7];
    const float* bskip = (const float*)d_in[8];
    float* out = (float*)d_out;

    const int postSmem = (2 * Hv * 32 + 2 * Hv * 16) * 4;     // 48 KB
    cudaFuncSetAttribute(post_kernel, cudaFuncAttributeMaxDynamicSharedMemorySize, postSmem);

    pre_kernel<<<512, 256>>>(h, Wpre, bpre, Wskip, bskip);
    agg_kernel<<<(ROWS / 8) * 2, 256>>>(e, graph);
    post_kernel<<<512, 256, postSmem>>>(Wpost, bpost, out);
}

// round 9
// speedup vs baseline: 1.8517x; 1.0280x over previous
#include <cuda_runtime.h>
#include <cstdint>

// Problem constants
#define Bv 8
#define Vv 256
#define Hv 128
#define ROWS (Bv*Vv)          // 2048
#define H4 (Hv/4)             // 32 float4 per row

typedef unsigned long long ull;

// Intermediates (device globals; no allocation allowed)
__device__ float g_h0[ROWS*Hv];                 // silu(h @ W_pre + b_pre)
__device__ float g_sk[ROWS*Hv];                 // silu(h @ W_skip + b_skip)
__device__ float g_part[2*ROWS*Hv];             // neigh partial maxes (2 j-halves)

__device__ __forceinline__ float silu_f(float x) {
    return x * (1.0f / (1.0f + __expf(-x)));
}

__device__ __forceinline__ void cp16(uint32_t dst, const void* src) {
    asm volatile("cp.async.cg.shared.global [%0], [%1], 16;" :: "r"(dst), "l"(src));
}
__device__ __forceinline__ void cp_commit() {
    asm volatile("cp.async.commit_group;");
}

__device__ __forceinline__ ull ffma2(ull a, ull b, ull c) {
    ull d;
    asm("fma.rn.f32x2 %0, %1, %2, %3;" : "=l"(d) : "l"(a), "l"(b), "l"(c));
    return d;
}
__device__ __forceinline__ ull pack2(float x, float y) {
    ull d; asm("mov.b64 %0, {%1, %2};" : "=l"(d) : "f"(x), "f"(y)); return d;
}
__device__ __forceinline__ float2 unpack2(ull v) {
    float2 r; asm("mov.b64 {%0, %1}, %2;" : "=f"(r.x), "=f"(r.y) : "l"(v)); return r;
}

// ---------------------------------------------------------------------------
// Kernel A: h0 = silu(h @ W_pre + b_pre), sk = silu(h @ W_skip + b_skip)
// 2-D tiled: 512 blocks (128 row-tiles x 4 col-tiles) x 128 threads.
// Block tile = 16 rows x 32 cols. Thread = 4 rows x 1 col x 2 matrices:
// per k ONE broadcast LDS.128 (4 rows) + 2 scalar LDS (wa, wb) -> 8 FMAs.
// W slices (16 KB each) + transposed h (8 KB) staged once; one sync.
// ---------------------------------------------------------------------------
__global__ void __launch_bounds__(128) pre_kernel(
    const float* __restrict__ h,
    const float* __restrict__ Wpre,  const float* __restrict__ bpre,
    const float* __restrict__ Wskip, const float* __restrict__ bskip)
{
    __shared__ float sWA[Hv * 32];       // 16 KB : sWA[k][c]
    __shared__ float sWB[Hv * 32];       // 16 KB
    __shared__ float hT[Hv * 16];        // 8 KB  : hT[k][r]

    const int tid  = threadIdx.x;
    const int c    = tid & 31;
    const int rg   = tid >> 5;           // 0..3 (4-row group)
    const int rowT = blockIdx.x >> 2;
    const int colT = blockIdx.x & 3;
    const int row0 = rowT * 16;
    const int col0 = colT * 32;

    // Stage W slices: 1024 float4 each, 8/thread each.
    const float4* WAg = (const float4*)Wpre;
    const float4* WBg = (const float4*)Wskip;
#pragma unroll
    for (int r = 0; r < 8; r++) {
        const int x = r * 128 + tid;           // x = k*8 + c4
        const int src = (x >> 3) * 32 + colT * 8 + (x & 7);
        ((float4*)sWA)[x] = WAg[src];
        ((float4*)sWB)[x] = WBg[src];
    }

    // Stage transposed h rows: 16 rows x 32 float4 = 512, 4/thread.
    const float4* h4 = (const float4*)h;
#pragma unroll
    for (int x = tid; x < 512; x += 128) {
        const int rr = x & 15, k4 = x >> 4;
        float4 v = h4[(row0 + rr) * H4 + k4];
        hT[(k4 * 4 + 0) * 16 + rr] = v.x;
        hT[(k4 * 4 + 1) * 16 + rr] = v.y;
        hT[(k4 * 4 + 2) * 16 + rr] = v.z;
        hT[(k4 * 4 + 3) * 16 + rr] = v.w;
    }
    __syncthreads();

    ull accA0, accA1, accB0, accB1;
    {
        const float bA = bpre[col0 + c], bB = bskip[col0 + c];
        accA0 = pack2(bA, bA); accA1 = accA0;
        accB0 = pack2(bB, bB); accB1 = accB0;
    }

#pragma unroll 16
    for (int k = 0; k < Hv; k++) {
        ulonglong2 hv = *(const ulonglong2*)&hT[k * 16 + 4 * rg];  // 4 rows, bcast
        const float wa = sWA[k * 32 + c];
        const float wb = sWB[k * 32 + c];
        const ull wa2 = pack2(wa, wa);
        const ull wb2 = pack2(wb, wb);
        accA0 = ffma2(hv.x, wa2, accA0);
        accA1 = ffma2(hv.y, wa2, accA1);
        accB0 = ffma2(hv.x, wb2, accB0);
        accB1 = ffma2(hv.y, wb2, accB1);
    }

    {
        float2 a0 = unpack2(accA0), a1 = unpack2(accA1);
        float2 b0 = unpack2(accB0), b1 = unpack2(accB1);
        const int row = row0 + 4 * rg;
        const int col = col0 + c;
        g_h0[(row + 0) * Hv + col] = silu_f(a0.x);
        g_h0[(row + 1) * Hv + col] = silu_f(a0.y);
        g_h0[(row + 2) * Hv + col] = silu_f(a1.x);
        g_h0[(row + 3) * Hv + col] = silu_f(a1.y);
        g_sk[(row + 0) * Hv + col] = silu_f(b0.x);
        g_sk[(row + 1) * Hv + col] = silu_f(b0.y);
        g_sk[(row + 2) * Hv + col] = silu_f(b1.x);
        g_sk[(row + 3) * Hv + col] = silu_f(b1.y);
    }
}

// ---------------------------------------------------------------------------
// Kernel B (dominant): partial neigh max over a 128-wide j-half.
// 512 blocks (b x 32 i-tiles x 2 j-halves) x 256 threads -> ALL resident
// (36 KB smem/block, no wave tail). h0 staged via cp.async double buffer.
// ---------------------------------------------------------------------------
__global__ void __launch_bounds__(256) agg_kernel(
    const float* __restrict__ e,
    const int*   __restrict__ graph)
{
    __shared__ float4 h0s[2][32 * H4];   // 2 x 16 KB
    __shared__ int    gsh[8][128];       // 4 KB

    const int tid  = threadIdx.x;
    const int hq   = tid & 31;           // float4 index in H
    const int isub = tid >> 5;           // 0..7
    const int b    = blockIdx.x >> 6;
    const int rem  = blockIdx.x & 63;
    const int i0   = (rem >> 1) * 8;
    const int jh   = rem & 1;
    const int j0   = jh * 128;
    const int i    = i0 + isub;

    // stage graph mask for this (i-tile, j-half): 1024 ints, 4/thread
#pragma unroll
    for (int x = tid; x < 8 * 128; x += 256) {
        gsh[x >> 7][x & 127] = graph[(b * Vv + i0 + (x >> 7)) * Vv + j0 + (x & 127)];
    }

    const float4* H0 = (const float4*)g_h0 + b * Vv * H4 + j0 * H4;
    const uint32_t sb0 = (uint32_t)__cvta_generic_to_shared(&h0s[0][0]);
    const uint32_t sb1 = (uint32_t)__cvta_generic_to_shared(&h0s[1][0]);

    // issue chunk c (32 j x 32 q = 1024 float4; 4 cp.async per thread)
    auto issue = [&](int c) {
        const uint32_t sb = (c & 1) ? sb1 : sb0;
#pragma unroll
        for (int r = 0; r < 4; r++) {
            const int x = r * 256 + tid;
            cp16(sb + x * 16, (const void*)(H0 + c * 1024 + x));
        }
        cp_commit();
    };
    issue(0);
    issue(1);

    const float4* Ep = (const float4*)e + ((size_t)(b * Vv + i) * Vv + j0) * H4 + hq;

    const float NEG_INF = __int_as_float(0xff800000);
    float4 acc = make_float4(NEG_INF, NEG_INF, NEG_INF, NEG_INF);

    for (int c = 0; c < 4; c++) {
        if (c == 3) asm volatile("cp.async.wait_group 0;");
        else        asm volatile("cp.async.wait_group 1;");
        __syncthreads();

        const float4* hb = h0s[c & 1];
        const int*    gm = &gsh[isub][c * 32];

#pragma unroll 8
        for (int jj = 0; jj < 32; jj++) {
            float4 ev = Ep[jj * H4];
            float4 hv = hb[jj * H4 + hq];
            if (gm[jj] != 0) { hv.x = 0.f; hv.y = 0.f; hv.z = 0.f; hv.w = 0.f; }
            acc.x = fmaxf(acc.x, ev.x * hv.x);
            acc.y = fmaxf(acc.y, ev.y * hv.y);
            acc.z = fmaxf(acc.z, ev.z * hv.z);
            acc.w = fmaxf(acc.w, ev.w * hv.w);
        }
        Ep += 32 * H4;

        __syncthreads();
        if (c + 2 < 4) issue(c + 2);
    }

    ((float4*)g_part)[((size_t)jh * ROWS + b * Vv + i) * H4 + hq] = acc;
}

// ---------------------------------------------------------------------------
// Kernel C: out = silu( sk + silu([h0,neigh] @ W_post + b_post) )
// 2-D tiled: 512 blocks (128 row-tiles x 4 col-tiles) x 128 threads.
// Block tile = 16 rows x 32 cols, thread = 4 rows x 1 col; per k ONE
// broadcast LDS.128 + 1 scalar LDS -> 4 FMAs. W_post slice (32 KB) + concat
// activations (16 KB, aT[k][16], k<128 h0, k>=128 neigh) staged once.
// ---------------------------------------------------------------------------
extern __shared__ float s_dyn[];

__global__ void __launch_bounds__(128) post_kernel(
    const float* __restrict__ Wpost, const float* __restrict__ bpost,
    float* __restrict__ out)
{
    float* sW = s_dyn;                    // sW[k][c], 256 x 32
    float* aT = s_dyn + 2 * Hv * 32;      // aT[k][r], 256 x 16

    const int tid  = threadIdx.x;
    const int c    = tid & 31;
    const int rg   = tid >> 5;            // 0..3
    const int rowT = blockIdx.x >> 2;
    const int colT = blockIdx.x & 3;
    const int row0 = rowT * 16;
    const int col0 = colT * 32;

    // Stage W slice: 2048 float4, 16/thread.
    const float4* Wg = (const float4*)Wpost;
#pragma unroll
    for (int r = 0; r < 16; r++) {
        const int x = r * 128 + tid;           // x = k*8 + c4
        ((float4*)sW)[x] = Wg[(x >> 3) * 32 + colT * 8 + (x & 7)];
    }

    // Stage transposed h0 and neigh: 512 float4 paths, 4/thread each.
    const float4* h04 = (const float4*)g_h0;
    const float4* gp  = (const float4*)g_part;
#pragma unroll
    for (int x = tid; x < 512; x += 128) {
        const int rr = x & 15, k4 = x >> 4;
        float4 v = h04[(row0 + rr) * H4 + k4];
        aT[(k4 * 4 + 0) * 16 + rr] = v.x;
        aT[(k4 * 4 + 1) * 16 + rr] = v.y;
        aT[(k4 * 4 + 2) * 16 + rr] = v.z;
        aT[(k4 * 4 + 3) * 16 + rr] = v.w;
        float4 p0 = gp[(row0 + rr) * H4 + k4];
        float4 p1 = gp[(size_t)ROWS * H4 + (row0 + rr) * H4 + k4];
        aT[(Hv + k4 * 4 + 0) * 16 + rr] = fmaxf(p0.x, p1.x);
        aT[(Hv + k4 * 4 + 1) * 16 + rr] = fmaxf(p0.y, p1.y);
        aT[(Hv + k4 * 4 + 2) * 16 + rr] = fmaxf(p0.z, p1.z);
        aT[(Hv + k4 * 4 + 3) * 16 + rr] = fmaxf(p0.w, p1.w);
    }
    __syncthreads();

    ull acc0, acc1;
    {
        const float bP = bpost[col0 + c];
        acc0 = pack2(bP, bP);
        acc1 = pack2(0.f, 0.f);
    }

#pragma unroll 16
    for (int k = 0; k < 2 * Hv; k++) {
        ulonglong2 av = *(const ulonglong2*)&aT[k * 16 + 4 * rg];  // 4 rows, bcast
        const float w = sW[k * 32 + c];
        const ull w2 = pack2(w, w);
        acc0 = ffma2(av.x, w2, acc0);
        acc1 = ffma2(av.y, w2, acc1);
    }

    {
        float2 v0 = unpack2(acc0), v1 = unpack2(acc1);
        const int row = row0 + 4 * rg;
        const int col = col0 + c;
        out[(row + 0) * Hv + col] = silu_f(g_sk[(row + 0) * Hv + col] + silu_f(v0.x));
        out[(row + 1) * Hv + col] = silu_f(g_sk[(row + 1) * Hv + col] + silu_f(v0.y));
        out[(row + 2) * Hv + col] = silu_f(g_sk[(row + 2) * Hv + col] + silu_f(v1.x));
        out[(row + 3) * Hv + col] = silu_f(g_sk[(row + 3) * Hv + col] + silu_f(v1.y));
    }
}

// ---------------------------------------------------------------------------
extern "C" void kernel_launch(void* const* d_in, const int* in_sizes, int n_in,
                              void* d_out, int out_size)
{
    const float* h     = (const float*)d_in[0];
    const float* e     = (const float*)d_in[1];
    const int*   graph = (const int*)  d_in[2];
    const float* Wpre  = (const float*)d_in[3];
    const float* bpre  = (const float*)d_in[4];
    const float* Wpost = (const float*)d_in[5];
    const float* bpost = (const float*)d_in[6];
    const float* Wskip = (const float*)d_in[7];
    const float* bskip = (const float*)d_in[8];
    float* out = (float*)d_out;

    const int postSmem = (2 * Hv * 32 + 2 * Hv * 16) * 4;     // 48 KB
    cudaFuncSetAttribute(post_kernel, cudaFuncAttributeMaxDynamicSharedMemorySize, postSmem);

    pre_kernel<<<512, 128>>>(h, Wpre, bpre, Wskip, bskip);
    agg_kernel<<<(ROWS / 8) * 2, 256>>>(e, graph);
    post_kernel<<<512, 128, postSmem>>>(Wpost, bpost, out);
}

// round 10
// speedup vs baseline: 2.4135x; 1.3034x over previous
#include <cuda_runtime.h>
#include <cstdint>

// Problem constants
#define Bv 8
#define Vv 256
#define Hv 128
#define ROWS (Bv*Vv)          // 2048
#define H4 (Hv/4)             // 32 float4 per row

typedef unsigned long long ull;

// Intermediates (device globals; no allocation allowed)
__device__ float g_h0[ROWS*Hv];                 // silu(h @ W_pre + b_pre)
__device__ float g_sk[ROWS*Hv];                 // silu(h @ W_skip + b_skip)
__device__ float g_part[2*ROWS*Hv];             // neigh partial maxes (2 j-halves)

__device__ __forceinline__ float silu_f(float x) {
    return x * (1.0f / (1.0f + __expf(-x)));
}

__device__ __forceinline__ void cp16(uint32_t dst, const void* src) {
    asm volatile("cp.async.cg.shared.global [%0], [%1], 16;" :: "r"(dst), "l"(src));
}
__device__ __forceinline__ void cp_commit() {
    asm volatile("cp.async.commit_group;");
}

__device__ __forceinline__ ull ffma2(ull a, ull b, ull c) {
    ull d;
    asm("fma.rn.f32x2 %0, %1, %2, %3;" : "=l"(d) : "l"(a), "l"(b), "l"(c));
    return d;
}
__device__ __forceinline__ ull pack2(float x, float y) {
    ull d; asm("mov.b64 %0, {%1, %2};" : "=l"(d) : "f"(x), "f"(y)); return d;
}
__device__ __forceinline__ float2 unpack2(ull v) {
    float2 r; asm("mov.b64 {%0, %1}, %2;" : "=f"(r.x), "=f"(r.y) : "l"(v)); return r;
}

// ---------------------------------------------------------------------------
// Kernel A: h0 = silu(h @ W_pre + b_pre), sk = silu(h @ W_skip + b_skip)
// 2-D tiled: 512 blocks (128 row-tiles x 4 col-tiles) x 128 threads.
// Block tile = 16 rows x 32 cols. Thread = 4 rows x 1 col x 2 matrices.
// ---------------------------------------------------------------------------
__global__ void __launch_bounds__(128) pre_kernel(
    const float* __restrict__ h,
    const float* __restrict__ Wpre,  const float* __restrict__ bpre,
    const float* __restrict__ Wskip, const float* __restrict__ bskip)
{
    __shared__ float sWA[Hv * 32];       // 16 KB : sWA[k][c]
    __shared__ float sWB[Hv * 32];       // 16 KB
    __shared__ float hT[Hv * 16];        // 8 KB  : hT[k][r]

    const int tid  = threadIdx.x;
    const int c    = tid & 31;
    const int rg   = tid >> 5;           // 0..3 (4-row group)
    const int rowT = blockIdx.x >> 2;
    const int colT = blockIdx.x & 3;
    const int row0 = rowT * 16;
    const int col0 = colT * 32;

    // Stage W slices: 1024 float4 each, 8/thread each.
    const float4* WAg = (const float4*)Wpre;
    const float4* WBg = (const float4*)Wskip;
#pragma unroll
    for (int r = 0; r < 8; r++) {
        const int x = r * 128 + tid;           // x = k*8 + c4
        const int src = (x >> 3) * 32 + colT * 8 + (x & 7);
        ((float4*)sWA)[x] = WAg[src];
        ((float4*)sWB)[x] = WBg[src];
    }

    // Stage transposed h rows: 16 rows x 32 float4 = 512, 4/thread.
    const float4* h4 = (const float4*)h;
#pragma unroll
    for (int x = tid; x < 512; x += 128) {
        const int rr = x & 15, k4 = x >> 4;
        float4 v = h4[(row0 + rr) * H4 + k4];
        hT[(k4 * 4 + 0) * 16 + rr] = v.x;
        hT[(k4 * 4 + 1) * 16 + rr] = v.y;
        hT[(k4 * 4 + 2) * 16 + rr] = v.z;
        hT[(k4 * 4 + 3) * 16 + rr] = v.w;
    }
    __syncthreads();

    ull accA0, accA1, accB0, accB1;
    {
        const float bA = bpre[col0 + c], bB = bskip[col0 + c];
        accA0 = pack2(bA, bA); accA1 = accA0;
        accB0 = pack2(bB, bB); accB1 = accB0;
    }

#pragma unroll 16
    for (int k = 0; k < Hv; k++) {
        ulonglong2 hv = *(const ulonglong2*)&hT[k * 16 + 4 * rg];  // 4 rows, bcast
        const float wa = sWA[k * 32 + c];
        const float wb = sWB[k * 32 + c];
        const ull wa2 = pack2(wa, wa);
        const ull wb2 = pack2(wb, wb);
        accA0 = ffma2(hv.x, wa2, accA0);
        accA1 = ffma2(hv.y, wa2, accA1);
        accB0 = ffma2(hv.x, wb2, accB0);
        accB1 = ffma2(hv.y, wb2, accB1);
    }

    {
        float2 a0 = unpack2(accA0), a1 = unpack2(accA1);
        float2 b0 = unpack2(accB0), b1 = unpack2(accB1);
        const int row = row0 + 4 * rg;
        const int col = col0 + c;
        g_h0[(row + 0) * Hv + col] = silu_f(a0.x);
        g_h0[(row + 1) * Hv + col] = silu_f(a0.y);
        g_h0[(row + 2) * Hv + col] = silu_f(a1.x);
        g_h0[(row + 3) * Hv + col] = silu_f(a1.y);
        g_sk[(row + 0) * Hv + col] = silu_f(b0.x);
        g_sk[(row + 1) * Hv + col] = silu_f(b0.y);
        g_sk[(row + 2) * Hv + col] = silu_f(b1.x);
        g_sk[(row + 3) * Hv + col] = silu_f(b1.y);
    }
}

// ---------------------------------------------------------------------------
// Kernel B (dominant): partial neigh max over a 128-wide j-half.
// 512 blocks (b x 32 i-tiles x 2 j-halves) x 256 threads -> ALL resident.
// NEW: e rows with graph!=0 contribute exactly 0 to the max, so their 512 B
// e-rows are NEVER LOADED (warp-uniform branch: warp index == isub == i).
// ~50% of rows are masked -> e DRAM traffic halved. Masked contribution (0)
// folded in once at the end via anyMasked flag. e loads use __ldcs (stream).
// ---------------------------------------------------------------------------
__global__ void __launch_bounds__(256) agg_kernel(
    const float* __restrict__ e,
    const int*   __restrict__ graph)
{
    __shared__ float4 h0s[2][32 * H4];   // 2 x 16 KB
    __shared__ int    gsh[8][128];       // 4 KB

    const int tid  = threadIdx.x;
    const int hq   = tid & 31;           // float4 index in H
    const int isub = tid >> 5;           // 0..7 == warp index
    const int b    = blockIdx.x >> 6;
    const int rem  = blockIdx.x & 63;
    const int i0   = (rem >> 1) * 8;
    const int jh   = rem & 1;
    const int j0   = jh * 128;
    const int i    = i0 + isub;

    // stage graph mask for this (i-tile, j-half): 1024 ints, 4/thread
#pragma unroll
    for (int x = tid; x < 8 * 128; x += 256) {
        gsh[x >> 7][x & 127] = graph[(b * Vv + i0 + (x >> 7)) * Vv + j0 + (x & 127)];
    }

    const float4* H0 = (const float4*)g_h0 + b * Vv * H4 + j0 * H4;
    const uint32_t sb0 = (uint32_t)__cvta_generic_to_shared(&h0s[0][0]);
    const uint32_t sb1 = (uint32_t)__cvta_generic_to_shared(&h0s[1][0]);

    // issue chunk c (32 j x 32 q = 1024 float4; 4 cp.async per thread)
    auto issue = [&](int c) {
        const uint32_t sb = (c & 1) ? sb1 : sb0;
#pragma unroll
        for (int r = 0; r < 4; r++) {
            const int x = r * 256 + tid;
            cp16(sb + x * 16, (const void*)(H0 + c * 1024 + x));
        }
        cp_commit();
    };
    issue(0);
    issue(1);

    const float4* Ep = (const float4*)e + ((size_t)(b * Vv + i) * Vv + j0) * H4 + hq;

    const float NEG_INF = __int_as_float(0xff800000);
    float4 acc = make_float4(NEG_INF, NEG_INF, NEG_INF, NEG_INF);
    int anyMasked = 0;

    for (int c = 0; c < 4; c++) {
        if (c == 3) asm volatile("cp.async.wait_group 0;");
        else        asm volatile("cp.async.wait_group 1;");
        __syncthreads();

        const float4* hb = h0s[c & 1];
        const int*    gm = &gsh[isub][c * 32];

#pragma unroll 8
        for (int jj = 0; jj < 32; jj++) {
            if (gm[jj] == 0) {               // warp-uniform branch
                float4 ev = __ldcs(&Ep[jj * H4]);
                float4 hv = hb[jj * H4 + hq];
                acc.x = fmaxf(acc.x, ev.x * hv.x);
                acc.y = fmaxf(acc.y, ev.y * hv.y);
                acc.z = fmaxf(acc.z, ev.z * hv.z);
                acc.w = fmaxf(acc.w, ev.w * hv.w);
            } else {
                anyMasked = 1;               // masked row contributes exactly 0
            }
        }
        Ep += 32 * H4;

        __syncthreads();
        if (c + 2 < 4) issue(c + 2);
    }

    if (anyMasked) {
        acc.x = fmaxf(acc.x, 0.0f);
        acc.y = fmaxf(acc.y, 0.0f);
        acc.z = fmaxf(acc.z, 0.0f);
        acc.w = fmaxf(acc.w, 0.0f);
    }

    ((float4*)g_part)[((size_t)jh * ROWS + b * Vv + i) * H4 + hq] = acc;
}

// ---------------------------------------------------------------------------
// Kernel C: out = silu( sk + silu([h0,neigh] @ W_post + b_post) )
// 2-D tiled: 512 blocks (128 row-tiles x 4 col-tiles) x 128 threads.
// neigh = max of the two j-half partials (note: partials may be -inf only if
// a half had no contributions at all; the other half then dominates or both
// halves' flags guarantee >= 0 when any mask exists; exact-max preserved).
// ---------------------------------------------------------------------------
extern __shared__ float s_dyn[];

__global__ void __launch_bounds__(128) post_kernel(
    const float* __restrict__ Wpost, const float* __restrict__ bpost,
    float* __restrict__ out)
{
    float* sW = s_dyn;                    // sW[k][c], 256 x 32
    float* aT = s_dyn + 2 * Hv * 32;      // aT[k][r], 256 x 16

    const int tid  = threadIdx.x;
    const int c    = tid & 31;
    const int rg   = tid >> 5;            // 0..3
    const int rowT = blockIdx.x >> 2;
    const int colT = blockIdx.x & 3;
    const int row0 = rowT * 16;
    const int col0 = colT * 32;

    // Stage W slice: 2048 float4, 16/thread.
    const float4* Wg = (const float4*)Wpost;
#pragma unroll
    for (int r = 0; r < 16; r++) {
        const int x = r * 128 + tid;           // x = k*8 + c4
        ((float4*)sW)[x] = Wg[(x >> 3) * 32 + colT * 8 + (x & 7)];
    }

    // Stage transposed h0 and neigh: 512 float4 paths, 4/thread each.
    const float4* h04 = (const float4*)g_h0;
    const float4* gp  = (const float4*)g_part;
#pragma unroll
    for (int x = tid; x < 512; x += 128) {
        const int rr = x & 15, k4 = x >> 4;
        float4 v = h04[(row0 + rr) * H4 + k4];
        aT[(k4 * 4 + 0) * 16 + rr] = v.x;
        aT[(k4 * 4 + 1) * 16 + rr] = v.y;
        aT[(k4 * 4 + 2) * 16 + rr] = v.z;
        aT[(k4 * 4 + 3) * 16 + rr] = v.w;
        float4 p0 = gp[(row0 + rr) * H4 + k4];
        float4 p1 = gp[(size_t)ROWS * H4 + (row0 + rr) * H4 + k4];
        aT[(Hv + k4 * 4 + 0) * 16 + rr] = fmaxf(p0.x, p1.x);
        aT[(Hv + k4 * 4 + 1) * 16 + rr] = fmaxf(p0.y, p1.y);
        aT[(Hv + k4 * 4 + 2) * 16 + rr] = fmaxf(p0.z, p1.z);
        aT[(Hv + k4 * 4 + 3) * 16 + rr] = fmaxf(p0.w, p1.w);
    }
    __syncthreads();

    ull acc0, acc1;
    {
        const float bP = bpost[col0 + c];
        acc0 = pack2(bP, bP);
        acc1 = pack2(0.f, 0.f);
    }

#pragma unroll 16
    for (int k = 0; k < 2 * Hv; k++) {
        ulonglong2 av = *(const ulonglong2*)&aT[k * 16 + 4 * rg];  // 4 rows, bcast
        const float w = sW[k * 32 + c];
        const ull w2 = pack2(w, w);
        acc0 = ffma2(av.x, w2, acc0);
        acc1 = ffma2(av.y, w2, acc1);
    }

    {
        float2 v0 = unpack2(acc0), v1 = unpack2(acc1);
        const int row = row0 + 4 * rg;
        const int col = col0 + c;
        out[(row + 0) * Hv + col] = silu_f(g_sk[(row + 0) * Hv + col] + silu_f(v0.x));
        out[(row + 1) * Hv + col] = silu_f(g_sk[(row + 1) * Hv + col] + silu_f(v0.y));
        out[(row + 2) * Hv + col] = silu_f(g_sk[(row + 2) * Hv + col] + silu_f(v1.x));
        out[(row + 3) * Hv + col] = silu_f(g_sk[(row + 3) * Hv + col] + silu_f(v1.y));
    }
}

// ---------------------------------------------------------------------------
extern "C" void kernel_launch(void* const* d_in, const int* in_sizes, int n_in,
                              void* d_out, int out_size)
{
    const float* h     = (const float*)d_in[0];
    const float* e     = (const float*)d_in[1];
    const int*   graph = (const int*)  d_in[2];
    const float* Wpre  = (const float*)d_in[3];
    const float* bpre  = (const float*)d_in[4];
    const float* Wpost = (const float*)d_in[5];
    const float* bpost = (const float*)d_in[6];
    const float* Wskip = (const float*)d_in[7];
    const float* bskip = (const float*)d_in[8];
    float* out = (float*)d_out;

    const int postSmem = (2 * Hv * 32 + 2 * Hv * 16) * 4;     // 48 KB
    cudaFuncSetAttribute(post_kernel, cudaFuncAttributeMaxDynamicSharedMemorySize, postSmem);

    pre_kernel<<<512, 128>>>(h, Wpre, bpre, Wskip, bskip);
    agg_kernel<<<(ROWS / 8) * 2, 256>>>(e, graph);
    post_kernel<<<512, 128, postSmem>>>(Wpost, bpost, out);
}